// round 1
// baseline (speedup 1.0000x reference)
#include <cuda_runtime.h>
#include <cstdint>

#define N_NODES 100000
#define E_EDGES 800000
#define P_PERM  200000
#define L_LEN   16
#define D_DIM   64
#define NUM_BOND 4

// ---------------- scratch (static device allocations are allowed) ------------
__device__ float g_Wf[L_LEN * D_DIM * D_DIM];                    // [a][b][c]  256KB
__device__ float g_BW[L_LEN * NUM_BOND * D_DIM];                 // [a][j][c]   16KB
__device__ float g_NW[(size_t)N_NODES * L_LEN * D_DIM];          // [n][a][c]  410MB

// ============================================================================
// K1: transpose weights -> Wf[a][b][c], and BW[a][j][c] = bond_emb[j] @ W[:,:,a]
// ============================================================================
__global__ void prep_kernel(const float* __restrict__ weights,
                            const float* __restrict__ bond_emb) {
    int idx = blockIdx.x * blockDim.x + threadIdx.x;
    if (idx < L_LEN * D_DIM * D_DIM) {
        int a = idx >> 12;
        int b = (idx >> 6) & 63;
        int c = idx & 63;
        g_Wf[idx] = weights[((b << 6) + c) * L_LEN + a];
    }
    if (idx < L_LEN * NUM_BOND * D_DIM) {
        int a = idx >> 8;
        int j = (idx >> 6) & 3;
        int c = idx & 63;
        float s = 0.f;
        #pragma unroll 8
        for (int b = 0; b < D_DIM; b++)
            s += bond_emb[j * D_DIM + b] * weights[((b << 6) + c) * L_LEN + a];
        g_BW[idx] = s;
    }
}

// ============================================================================
// K2: NW[n][a][c] = sum_b nfeat[n,b] * Wf[a][b][c]
// grid = (ceil(N/128), 16 a-slices), 128 threads, 8x8 microtile per thread.
// ============================================================================
#define XSP 132   // 128 n + pad (keeps 16B alignment: 132 % 4 == 0)
#define WSP 68    // 64 c + pad

__global__ __launch_bounds__(128)
void nw_gemm_kernel(const float* __restrict__ nfeat) {
    extern __shared__ float smem2[];
    float* xs = smem2;              // [64 b][XSP]  (n inner)
    float* ws = smem2 + 64 * XSP;   // [64 b][WSP]  (c inner)

    const int tid = threadIdx.x;
    const int n0  = blockIdx.x * 128;
    const int a   = blockIdx.y;

    // load W slice: 4096 floats
    {
        const float4* wsrc = (const float4*)&g_Wf[a * 4096];
        #pragma unroll
        for (int i = tid; i < 1024; i += 128) {
            float4 v = wsrc[i];
            int b = i >> 4;
            int c = (i & 15) << 2;
            *(float4*)&ws[b * WSP + c] = v;
        }
    }
    // load nfeat tile transposed: xs[b][n]
    #pragma unroll
    for (int i = tid; i < 2048; i += 128) {
        int n  = i >> 4;
        int c4 = (i & 15) << 2;
        float4 v = make_float4(0.f, 0.f, 0.f, 0.f);
        if (n0 + n < N_NODES)
            v = *(const float4*)&nfeat[(size_t)(n0 + n) * D_DIM + c4];
        xs[(c4 + 0) * XSP + n] = v.x;
        xs[(c4 + 1) * XSP + n] = v.y;
        xs[(c4 + 2) * XSP + n] = v.z;
        xs[(c4 + 3) * XSP + n] = v.w;
    }
    __syncthreads();

    const int tn = (tid >> 3) << 3;   // 0..120
    const int tc = (tid & 7) << 3;    // 0..56

    float acc[8][8];
    #pragma unroll
    for (int i = 0; i < 8; i++)
        #pragma unroll
        for (int j = 0; j < 8; j++) acc[i][j] = 0.f;

    #pragma unroll 4
    for (int k = 0; k < 64; k++) {
        float4 x0 = *(const float4*)&xs[k * XSP + tn];
        float4 x1 = *(const float4*)&xs[k * XSP + tn + 4];
        float4 w0 = *(const float4*)&ws[k * WSP + tc];
        float4 w1 = *(const float4*)&ws[k * WSP + tc + 4];
        float xv[8] = {x0.x, x0.y, x0.z, x0.w, x1.x, x1.y, x1.z, x1.w};
        float wv[8] = {w0.x, w0.y, w0.z, w0.w, w1.x, w1.y, w1.z, w1.w};
        #pragma unroll
        for (int i = 0; i < 8; i++)
            #pragma unroll
            for (int j = 0; j < 8; j++)
                acc[i][j] += xv[i] * wv[j];
    }

    #pragma unroll
    for (int i = 0; i < 8; i++) {
        int n = n0 + tn + i;
        if (n < N_NODES) {
            float* dst = &g_NW[((size_t)n << 10) + (a << 6) + tc];
            *(float4*)(dst + 0) = make_float4(acc[i][0], acc[i][1], acc[i][2], acc[i][3]);
            *(float4*)(dst + 4) = make_float4(acc[i][4], acc[i][5], acc[i][6], acc[i][7]);
        }
    }
}

// ============================================================================
// K3: fused gather + einsum-assembly + relu + w_lin + deg-MLP gate + pool scatter
// 256 threads (8 warps), each warp processes 4 batches of 8 permutations.
// ============================================================================
#define FULLM 0xffffffffu

__global__ __launch_bounds__(256)
void fused_kernel(const float* __restrict__ degs,
                  const float* __restrict__ n2p_val,
                  const float* __restrict__ e2p_val,
                  const float* __restrict__ pool_val,
                  const float* __restrict__ bias,
                  const float* __restrict__ w_deg0,
                  const float* __restrict__ b_deg0,
                  const float* __restrict__ w_deg1,
                  const float* __restrict__ b_deg1,
                  const float* __restrict__ w_lin,
                  const float* __restrict__ b_lin,
                  const int*   __restrict__ edge_feat_idx,
                  const int*   __restrict__ n2p_col,
                  const int*   __restrict__ e2p_col,
                  const int*   __restrict__ pool_row,
                  float*       __restrict__ out) {
    extern __shared__ float smem[];
    float* s_BW     = smem;              // 4096  [a][j][c]
    float* s_wlinT  = s_BW + 4096;       // 4096  [k][c]
    float* s_wdeg1T = s_wlinT + 4096;    // 8192  [k][c]
    float* s_wdeg0  = s_wdeg1T + 8192;   // 512   [k][s]
    float* s_bdeg0  = s_wdeg0 + 512;     // 128
    float* s_bias   = s_bdeg0 + 128;     // 64
    float* s_blin   = s_bias + 64;       // 64
    float* s_bdeg1  = s_blin + 64;       // 64
    float* s_h      = s_bdeg1 + 64;      // 8 warps * 8p * 64 = 4096
    float* s_t      = s_h + 4096;        // 8 warps * 8p * 32 = 2048

    const int tid = threadIdx.x;
    // ---- stage constants into shared memory ----
    #pragma unroll
    for (int i = tid; i < 4096; i += 256) s_BW[i] = g_BW[i];
    #pragma unroll
    for (int i = tid; i < 4096; i += 256) {           // transpose w_lin -> [k][c]
        int k = i >> 6, c = i & 63;
        s_wlinT[i] = w_lin[c * 64 + k];
    }
    #pragma unroll
    for (int i = tid; i < 8192; i += 256) {           // transpose w_deg1 -> [k][c]
        int k = i >> 6, c = i & 63;
        s_wdeg1T[i] = w_deg1[c * 128 + k];
    }
    #pragma unroll
    for (int i = tid; i < 512; i += 256) s_wdeg0[i] = w_deg0[i];
    if (tid < 128) s_bdeg0[tid] = b_deg0[tid];
    if (tid < 64) {
        s_bias[tid]  = bias[tid];
        s_blin[tid]  = b_lin[tid];
        s_bdeg1[tid] = b_deg1[tid];
    }
    __syncthreads();

    const int warp = tid >> 5;
    const int lane = tid & 31;
    const int c0   = lane << 1;
    float* sh = s_h + warp * 512;   // [8p][64]
    float* st = s_t + warp * 256;   // [8p][32]

    const int pwarp = (blockIdx.x * 8 + warp) * 32;

    for (int b = 0; b < 4; b++) {
        const int p0 = pwarp + b * 8;
        float ds[8][4];

        // ---------- phase 1: gather NW rows + BW lookup, build relu(h) ----------
        for (int pp = 0; pp < 8; pp++) {
            int p = p0 + pp;
            bool valid = p < P_PERM;
            size_t ib = (size_t)(valid ? p : 0) * 16;
            int nc = 0, ec = 0;
            float vn = 0.f, ve = 0.f;
            if (lane < 16) {
                nc = n2p_col[ib + lane];
                vn = valid ? n2p_val[ib + lane] : 0.f;
                ec = e2p_col[ib + lane];
                ve = valid ? e2p_val[ib + lane] : 0.f;
            }
            int bj = (lane < 16) ? edge_feat_idx[ec] : 0;
            float dsv = 0.f;
            if (lane < 16 && (lane % 5) == 0) dsv = vn * degs[nc];
            ds[pp][0] = __shfl_sync(FULLM, dsv, 0);
            ds[pp][1] = __shfl_sync(FULLM, dsv, 5);
            ds[pp][2] = __shfl_sync(FULLM, dsv, 10);
            ds[pp][3] = __shfl_sync(FULLM, dsv, 15);

            float a0 = s_bias[c0], a1 = s_bias[c0 + 1];
            #pragma unroll
            for (int a = 0; a < 16; a++) {
                int   nca = __shfl_sync(FULLM, nc, a);
                float vna = __shfl_sync(FULLM, vn, a);
                int   bja = __shfl_sync(FULLM, bj, a);
                float vea = __shfl_sync(FULLM, ve, a);
                float2 nw = *(const float2*)&g_NW[((size_t)nca << 10) + (a << 6) + c0];
                float2 bw = *(const float2*)&s_BW[((a << 2) + bja) * 64 + c0];
                a0 += vna * nw.x + vea * bw.x;
                a1 += vna * nw.y + vea * bw.y;
            }
            sh[pp * 64 + c0]     = fmaxf(a0, 0.f);
            sh[pp * 64 + c0 + 1] = fmaxf(a1, 0.f);
        }
        __syncwarp();

        // ---------- phase 2: h2 = relu(h) @ w_lin^T + b_lin (batched over 8 p) ----------
        float h2a0[8], h2a1[8];
        #pragma unroll
        for (int pp = 0; pp < 8; pp++) { h2a0[pp] = s_blin[c0]; h2a1[pp] = s_blin[c0 + 1]; }
        #pragma unroll
        for (int k = 0; k < 64; k += 4) {
            float2 v0 = *(const float2*)&s_wlinT[(k + 0) * 64 + c0];
            float2 v1 = *(const float2*)&s_wlinT[(k + 1) * 64 + c0];
            float2 v2 = *(const float2*)&s_wlinT[(k + 2) * 64 + c0];
            float2 v3 = *(const float2*)&s_wlinT[(k + 3) * 64 + c0];
            #pragma unroll
            for (int pp = 0; pp < 8; pp++) {
                float4 hv = *(const float4*)&sh[pp * 64 + k];
                h2a0[pp] += hv.x * v0.x + hv.y * v1.x + hv.z * v2.x + hv.w * v3.x;
                h2a1[pp] += hv.x * v0.y + hv.y * v1.y + hv.z * v2.y + hv.w * v3.y;
            }
        }

        // ---------- phase 3: gate g = relu(ds @ w_deg0^T + b_deg0) @ w_deg1^T + b_deg1 ----------
        float g0[8], g1[8];
        #pragma unroll
        for (int pp = 0; pp < 8; pp++) { g0[pp] = s_bdeg1[c0]; g1[pp] = s_bdeg1[c0 + 1]; }
        for (int q = 0; q < 4; q++) {
            int k = q * 32 + lane;
            float4 w0 = *(const float4*)&s_wdeg0[k * 4];
            float b0 = s_bdeg0[k];
            #pragma unroll
            for (int pp = 0; pp < 8; pp++) {
                float t = ds[pp][0] * w0.x + ds[pp][1] * w0.y +
                          ds[pp][2] * w0.z + ds[pp][3] * w0.w + b0;
                st[pp * 32 + lane] = fmaxf(t, 0.f);
            }
            __syncwarp();
            #pragma unroll
            for (int kk = 0; kk < 32; kk += 4) {
                int kg = q * 32 + kk;
                float2 u0 = *(const float2*)&s_wdeg1T[(kg + 0) * 64 + c0];
                float2 u1 = *(const float2*)&s_wdeg1T[(kg + 1) * 64 + c0];
                float2 u2 = *(const float2*)&s_wdeg1T[(kg + 2) * 64 + c0];
                float2 u3 = *(const float2*)&s_wdeg1T[(kg + 3) * 64 + c0];
                #pragma unroll
                for (int pp = 0; pp < 8; pp++) {
                    float4 tv = *(const float4*)&st[pp * 32 + kk];
                    g0[pp] += tv.x * u0.x + tv.y * u1.x + tv.z * u2.x + tv.w * u3.x;
                    g1[pp] += tv.x * u0.y + tv.y * u1.y + tv.z * u2.y + tv.w * u3.y;
                }
            }
            __syncwarp();
        }

        // ---------- phase 4: scale by gate and pool_val, scatter-add ----------
        for (int pp = 0; pp < 8; pp++) {
            int p = p0 + pp;
            if (p < P_PERM) {
                float pv = pool_val[p];
                int   pr = pool_row[p];
                atomicAdd(&out[(size_t)pr * 64 + c0],     pv * h2a0[pp] * g0[pp]);
                atomicAdd(&out[(size_t)pr * 64 + c0 + 1], pv * h2a1[pp] * g1[pp]);
            }
        }
    }
}

// ============================================================================
extern "C" void kernel_launch(void* const* d_in, const int* in_sizes, int n_in,
                              void* d_out, int out_size) {
    const float* nfeat         = (const float*)d_in[0];
    const float* degs          = (const float*)d_in[1];
    const float* n2p_val       = (const float*)d_in[2];
    const float* e2p_val       = (const float*)d_in[3];
    const float* pool_val      = (const float*)d_in[4];
    const float* weights       = (const float*)d_in[5];
    const float* bias          = (const float*)d_in[6];
    const float* w_deg0        = (const float*)d_in[7];
    const float* b_deg0        = (const float*)d_in[8];
    const float* w_deg1        = (const float*)d_in[9];
    const float* b_deg1        = (const float*)d_in[10];
    const float* w_lin         = (const float*)d_in[11];
    const float* b_lin         = (const float*)d_in[12];
    const float* bond_emb      = (const float*)d_in[13];
    const int*   edge_feat_idx = (const int*)d_in[14];
    const int*   n2p_col       = (const int*)d_in[16];
    const int*   e2p_col       = (const int*)d_in[18];
    const int*   pool_row      = (const int*)d_in[19];
    float* out = (float*)d_out;

    // out has rows never touched by pool -> must be zero
    cudaMemsetAsync(d_out, 0, (size_t)out_size * sizeof(float), 0);

    // K1: weight transpose + bond @ W precompute
    prep_kernel<<<256, 256>>>(weights, bond_emb);

    // K2: NW = nfeat @ W  (per a-slice)
    const int k2_smem = (64 * XSP + 64 * WSP) * (int)sizeof(float);  // 51200 B
    cudaFuncSetAttribute(nw_gemm_kernel, cudaFuncAttributeMaxDynamicSharedMemorySize, k2_smem);
    dim3 g2((N_NODES + 127) / 128, L_LEN);
    nw_gemm_kernel<<<g2, 128, k2_smem>>>(nfeat);

    // K3: fused gather + epilogues + scatter
    const int k3_smem = 23360 * (int)sizeof(float);                  // 93440 B
    cudaFuncSetAttribute(fused_kernel, cudaFuncAttributeMaxDynamicSharedMemorySize, k3_smem);
    int g3 = (P_PERM + 255) / 256;  // 8 warps * 32 p per CTA
    fused_kernel<<<g3, 256, k3_smem>>>(degs, n2p_val, e2p_val, pool_val, bias,
                                       w_deg0, b_deg0, w_deg1, b_deg1,
                                       w_lin, b_lin,
                                       edge_feat_idx, n2p_col, e2p_col, pool_row,
                                       out);
}